// round 11
// baseline (speedup 1.0000x reference)
#include <cuda_runtime.h>
#include <math.h>

#define T_STEPS 256
typedef unsigned long long u64t;

struct Sc {
    float D22[32 * 32];
    float M[32 * 32];
    float Rinv[32 * 32];
    float vr[160 * 32];
    float T1[160 * 32];
    float H[160 * 160];
    float invLam[32];
};
__device__ Sc g_s;

// Weight image: WA 3072 | WX 8192 | WYF 4096 | DC 1024 = 16384 floats (64 KB)
#define OFF_WA 0
#define OFF_WX 3072
#define OFF_WY 11264
#define OFF_DC 15360
__device__ __align__(16) float g_params[16384];

__device__ __forceinline__ u64t f2_fma(u64t a, u64t b, u64t c) {
    u64t d; asm("fma.rn.f32x2 %0,%1,%2,%3;" : "=l"(d) : "l"(a), "l"(b), "l"(c)); return d;
}
__device__ __forceinline__ float f2_fold(u64t v) {
    float lo, hi; asm("mov.b64 {%0,%1},%2;" : "=f"(lo), "=f"(hi) : "l"(v));
    return lo + hi;
}
// tanh via ex2+rcp (abs err ~1e-7)
__device__ __forceinline__ float tanh_fast(float x) {
    float t = x * 2.885390081777926814f;
    float e; asm("ex2.approx.f32 %0,%1;" : "=f"(e) : "f"(t));
    float r; asm("rcp.approx.f32 %0,%1;" : "=f"(r) : "f"(e + 1.0f));
    return fmaf(-2.0f, r, 1.0f);
}

// ---------------- Gauss-Jordan (fp64, warp-parallel partial pivot) ----------------
__device__ void gj_invert(double* aug, int N, double* mv, int* s_piv, double* s_ipv) {
    const int tid = threadIdx.x, NT = blockDim.x;
    const int ld = 2 * N;
    for (int k = 0; k < N; k++) {
        if (tid < 32) {
            double best = -1.0; int bi = k;
            for (int r = k + tid; r < N; r += 32) {
                double v = fabs(aug[r * ld + k]);
                if (v > best) { best = v; bi = r; }
            }
            for (int o = 16; o; o >>= 1) {
                double ob = __shfl_down_sync(0xffffffffu, best, o);
                int    oi = __shfl_down_sync(0xffffffffu, bi, o);
                if (ob > best) { best = ob; bi = oi; }
            }
            if (tid == 0) *s_piv = bi;
        }
        __syncthreads();
        int p = *s_piv;
        if (p != k)
            for (int j = tid; j < ld; j += NT) {
                double tv = aug[k * ld + j];
                aug[k * ld + j] = aug[p * ld + j];
                aug[p * ld + j] = tv;
            }
        __syncthreads();
        if (tid == 0) *s_ipv = 1.0 / aug[k * ld + k];
        __syncthreads();
        double ipv = *s_ipv;
        for (int j = tid; j < ld; j += NT) aug[k * ld + j] *= ipv;
        __syncthreads();
        for (int r = tid; r < N; r += NT) mv[r] = aug[r * ld + k];
        __syncthreads();
        for (int idx = tid; idx < N * ld; idx += NT) {
            int r = idx / ld;
            if (r != k) {
                int j = idx - r * ld;
                aug[idx] -= mv[r] * aug[k * ld + j];
            }
        }
        __syncthreads();
    }
}

// ---------------- Setup A (1 block) ----------------
__global__ void ren_setup_a(const float* __restrict__ B2, const float* __restrict__ C2,
                            const float* __restrict__ D12, const float* __restrict__ L,
                            const float* __restrict__ U, const float* __restrict__ D21,
                            const float* __restrict__ gamma) {
    extern __shared__ double sd[];
    double* aug = sd;
    double* mv  = sd + 64 * 128;
    __shared__ int s_piv;
    __shared__ double s_ipv;
    const int tid = threadIdx.x, NT = blockDim.x;
    const float g = gamma[0];

    for (int idx = tid; idx < 1024; idx += NT) {
        int i = idx >> 5, j = idx & 31;
        float acc = (i == j) ? (g + 1.0f) : 0.0f;
        for (int k = 0; k < 32; k++) acc += L[k * 32 + i] * L[k * 32 + j];
        acc += U[i * 32 + j] - U[j * 32 + i];
        g_s.D22[idx] = acc;
    }
    __syncthreads();
    for (int idx = tid; idx < 32 * 64; idx += NT) {
        int i = idx >> 6, j = idx & 63;
        double v;
        if (j < 32) {
            float s = 0.0f;
            for (int k = 0; k < 32; k++) s += g_s.D22[k * 32 + i] * g_s.D22[k * 32 + j];
            v = (double)g_s.D22[i * 32 + j] + (double)g_s.D22[j * 32 + i] - 1e-4 * (double)s;
            if (i == j) v += -2.0 * (double)g;
        } else v = ((j - 32) == i) ? 1.0 : 0.0;
        aug[idx] = v;
    }
    __syncthreads();
    gj_invert(aug, 32, mv, &s_piv, &s_ipv);
    for (int idx = tid; idx < 1024; idx += NT) {
        int i = idx >> 5, j = idx & 31;
        g_s.Rinv[idx] = (float)aug[i * 64 + 32 + j];
    }
    for (int idx = tid; idx < 1024; idx += NT) {
        int i = idx >> 5, j = idx & 31;
        g_s.M[idx] = ((i == j) ? 1.0f : 0.0f) - 1e-4f * g_s.D22[j * 32 + i];
    }
    __syncthreads();
    for (int idx = tid; idx < 160 * 32; idx += NT) {
        int r = idx >> 5, c = idx & 31;
        float v;
        if (r < 64) {
            float s = 0.0f;
            for (int k = 0; k < 32; k++) s += g_s.M[c * 32 + k] * C2[k * 64 + r];
            v = s;
        } else if (r < 96) {
            int rr = r - 64;
            float s = 0.0f;
            for (int k = 0; k < 32; k++) s += g_s.M[c * 32 + k] * D21[k * 32 + rr];
            v = s - D12[rr * 32 + c];
        } else v = B2[(r - 96) * 32 + c];
        g_s.vr[idx] = v;
    }
    __syncthreads();
    for (int idx = tid; idx < 160 * 32; idx += NT) {
        int r = idx >> 5, c = idx & 31;
        float s = 0.0f;
        for (int k = 0; k < 32; k++) s += g_s.vr[r * 32 + k] * g_s.Rinv[k * 32 + c];
        g_s.T1[idx] = s;
    }
}

// ---------------- Setup B (160 blocks) ----------------
__global__ void ren_setup_b(const float* __restrict__ X, const float* __restrict__ C2,
                            const float* __restrict__ D21) {
    __shared__ float Xa[160];
    __shared__ float T1a[32];
    __shared__ float vqa[32];
    const int a = blockIdx.x;
    const int tid = threadIdx.x;
    for (int k = tid; k < 160; k += blockDim.x) Xa[k] = X[k * 160 + a];
    if (tid < 32) {
        T1a[tid] = g_s.T1[a * 32 + tid];
        float vq = 0.0f;
        if (a < 64) vq = C2[tid * 64 + a];
        else if (a < 96) vq = D21[tid * 32 + (a - 64)];
        vqa[tid] = vq;
    }
    __syncthreads();
    for (int b = tid; b < 160; b += blockDim.x) {
        float gsum = 0.0f;
        for (int k = 0; k < 160; k++) gsum += Xa[k] * X[k * 160 + b];
        float pr = 0.0f;
        for (int c = 0; c < 32; c++) pr += T1a[c] * g_s.vr[b * 32 + c];
        float q = 0.0f;
        if (b < 96)
            for (int c = 0; c < 32; c++) {
                float vb = (b < 64) ? C2[c * 64 + b] : D21[c * 32 + (b - 64)];
                q += vqa[c] * vb;
            }
        float h = gsum + pr + 1e-4f * q;
        if (a == b) h += 1e-3f;
        g_s.H[a * 160 + b] = h;
    }
}

// ---------------- Setup CD (64 blocks x 256) ----------------
// Each block assembles E, runs GJ64 locally, builds its 256-entry weight slice.
// WYF = y folded through xn: [C2*A_x | C2*A_w + D21 | C2*A_u + D22].
// FIX vs R10: CE = C2 @ Einv precomputed cooperatively into shared memory
// (was recomputed 64x per element -> setup_cd cost ~270 us).
__global__ void ren_setup_cd(const float* __restrict__ Y, const float* __restrict__ B2,
                             const float* __restrict__ C2, const float* __restrict__ D12,
                             const float* __restrict__ D21) {
    extern __shared__ double sd[];
    double* aug = sd;
    double* mv  = sd + 64 * 128;
    __shared__ int s_piv;
    __shared__ double s_ipv;
    __shared__ float CE[32 * 64];   // C2 @ Einv
    const int tid = threadIdx.x, NT = blockDim.x;

    for (int idx = tid; idx < 64 * 128; idx += NT) {
        int i = idx >> 7, j = idx & 127;
        double v;
        if (j < 64)
            v = 0.5 * ((double)g_s.H[i * 160 + j] + (double)g_s.H[(96 + i) * 160 + (96 + j)]
                       + (double)Y[i * 64 + j] - (double)Y[j * 64 + i]);
        else v = ((j - 64) == i) ? 1.0 : 0.0;
        aug[idx] = v;
    }
    __syncthreads();
    gj_invert(aug, 64, mv, &s_piv, &s_ipv);

#define EINV(r, c) ((float)aug[(r) * 128 + 64 + (c)])
    // CE[i][n] = sum_m C2[i][m] * Einv[m][n]
    for (int idx = tid; idx < 32 * 64; idx += NT) {
        int i = idx >> 6, n = idx & 63;
        float s = 0.0f;
        for (int m = 0; m < 64; m++) s += C2[i * 64 + m] * EINV(m, n);
        CE[idx] = s;
    }
    __syncthreads();

    const int g = blockIdx.x * 256 + tid;   // 0..16383
    if (g < 8192) {
        // WX: float4[j*32+lane] = (rowA c0, rowA c1, rowB c0, rowB c1)
        int e = g;
        int comp = e & 3, r = e >> 2, j = r >> 5, lane = r & 31;
        int row = (comp < 2) ? lane : lane + 32;
        int c = comp & 1;
        float s = 0.0f;
        if (j < 16) {
            int col = 2 * j + c;
            for (int m = 0; m < 64; m++) s += EINV(row, m) * B2[m * 32 + col];
        } else if (j < 32) {
            int col = 2 * (j - 16) + c;
            for (int m = 0; m < 64; m++) s += EINV(row, m) * g_s.H[(96 + m) * 160 + 64 + col];
        } else {
            int col = 2 * (j - 32) + c;
            for (int m = 0; m < 64; m++) s += EINV(row, m) * g_s.H[(96 + m) * 160 + col];
        }
        g_params[OFF_WX + e] = s;
    } else if (g < 11264) {
        // WA: float2[j*32+i]; j<16 u (D12), else x (C1=-H21); * invLam[i]
        int e = g - 8192;
        int c = e & 1, r = e >> 1, j = r >> 5, i = r & 31;
        float invLam = 1.0f / (0.5f * g_s.H[(64 + i) * 160 + (64 + i)]);
        float v;
        if (j < 16) v = D12[i * 32 + 2 * j + c];
        else        v = -g_s.H[(64 + i) * 160 + 2 * (j - 16) + c];
        g_params[OFF_WA + e] = v * invLam;
    } else if (g < 15360) {
        // WYF: float2[j*32+i]; j<16 u: CE@B2 + D22; j<32 w: CE@H32 + D21;
        //                      j>=32 x: CE@H31
        int e = g - 11264;
        int c = e & 1, r = e >> 1, j = r >> 5, i = r & 31;
        int col;
        float val;
        if (j < 16)      { col = 2 * j + c;        val = g_s.D22[i * 32 + col]; }
        else if (j < 32) { col = 2 * (j - 16) + c; val = D21[i * 32 + col]; }
        else             { col = 2 * (j - 32) + c; val = 0.0f; }
        float acc = 0.0f;
        for (int n = 0; n < 64; n++) {
            float sv;
            if (j < 16)      sv = B2[n * 32 + col];
            else if (j < 32) sv = g_s.H[(96 + n) * 160 + 64 + col];
            else             sv = g_s.H[(96 + n) * 160 + col];
            acc += CE[i * 64 + n] * sv;
        }
        g_params[OFF_WY + e] = val + acc;
    } else {
        // DC: float[i*32+l] = (l>i) ? -H22[l][i]/Lam[l] : 0
        int e = g - 15360;
        int i = e >> 5, l = e & 31;
        float invLam = 1.0f / (0.5f * g_s.H[(64 + l) * 160 + (64 + l)]);
        g_params[OFF_DC + e] =
            (l > i) ? (-g_s.H[(64 + l) * 160 + (64 + i)] * invLam) : 0.0f;
    }
#undef EINV
}

// ---------------------------------------------------------------------------
// Main: R10 structure (E=2, 8 warps, 128 blocks, y folded into x-phase) with
// ONE change: WA weights read from smem in MATA (wa_r register array removed)
// to drop register pressure from the 255 cap and let ptxas pipeline the
// MATXY load batches. dc_r (32 regs) kept.
// ---------------------------------------------------------------------------
__global__ void __launch_bounds__(256, 1)
ren_main(const float* __restrict__ u_in, const float* __restrict__ x0,
         float* __restrict__ y_out) {
    extern __shared__ float sm[];
    {
        float4* dst = (float4*)sm;
        const float4* src = (const float4*)g_params;
        for (int i = threadIdx.x; i < 4096; i += blockDim.x) dst[i] = src[i];
    }
    const int warp = threadIdx.x >> 5;
    const int lane = threadIdx.x & 31;
    float* fS = sm + 16384 + warp * 384;
    const float4* SA = (const float4*)fS;
    __syncthreads();

    float dc_r[32];
    #pragma unroll
    for (int i = 0; i < 32; i++)
        dc_r[i] = sm[OFF_DC + i * 32 + lane];

    const int e0 = (blockIdx.x * 8 + warp) * 2;
    const float* up0 = u_in + (size_t)(e0 + 0) * (T_STEPS * 32);
    const float* up1 = u_in + (size_t)(e0 + 1) * (T_STEPS * 32);
    float* yp0 = y_out + (size_t)(e0 + 0) * (T_STEPS * 32) + lane;
    float* yp1 = y_out + (size_t)(e0 + 1) * (T_STEPS * 32) + lane;

    // init x state (kp 64..95)
    {
        int ia = (64 + (lane >> 1)) * 4 + (lane & 1);
        int ib = (80 + (lane >> 1)) * 4 + (lane & 1);
        fS[ia]     = x0[(e0 + 0) * 64 + lane];
        fS[ia + 2] = x0[(e0 + 1) * 64 + lane];
        fS[ib]     = x0[(e0 + 0) * 64 + 32 + lane];
        fS[ib + 2] = x0[(e0 + 1) * 64 + 32 + lane];
    }
    float uc0 = up0[lane], uc1 = up1[lane];

    const int idxu = (32 + (lane >> 1)) * 4 + (lane & 1);
    const int idxw = (48 + (lane >> 1)) * 4 + (lane & 1);
    const int idxa = (64 + (lane >> 1)) * 4 + (lane & 1);
    const int idxb = (80 + (lane >> 1)) * 4 + (lane & 1);

#define LD2(p)  (*(const ulonglong2*)(p))
// a-phase state map: j<16 -> u at kp 32+j; j>=16 -> x at kp 48+j (=64..95)
#define MATA(kp, j) { \
    u64t wa = *(const u64t*)(sm + OFF_WA + ((j) * 32 + lane) * 2); \
    ulonglong2 s = LD2(SA + (kp)); \
    av0 = f2_fma(wa, s.x, av0); av1 = f2_fma(wa, s.y, av1); }
// combined x+y op: one state load feeds xn rowA, xn rowB, y row
#define MATXY(j) { \
    ulonglong2 wv = *(const ulonglong2*)(sm + OFF_WX + ((j) * 32 + lane) * 4); \
    u64t wy = *(const u64t*)(sm + OFF_WY + ((j) * 32 + lane) * 2); \
    ulonglong2 s  = LD2(SA + 32 + (j)); \
    xA0 = f2_fma(wv.x, s.x, xA0); xA1 = f2_fma(wv.x, s.y, xA1); \
    xB0 = f2_fma(wv.y, s.x, xB0); xB1 = f2_fma(wv.y, s.y, xB1); \
    yv0 = f2_fma(wy, s.x, yv0); yv1 = f2_fma(wy, s.y, yv1); }
#define CHAIN(i) { \
    float t0 = tanh_fast(a0), t1 = tanh_fast(a1); \
    t0 = __shfl_sync(0xffffffffu, t0, (i)); t1 = __shfl_sync(0xffffffffu, t1, (i)); \
    float d = dc_r[i]; \
    a0 = fmaf(d, t0, a0); a1 = fmaf(d, t1, a1); }

    for (int t = 0; t < T_STEPS; t++) {
        fS[idxu] = uc0; fS[idxu + 2] = uc1;
        int tn = (t < T_STEPS - 1) ? (t + 1) : t;
        float un0 = up0[tn * 32 + lane], un1 = up1[tn * 32 + lane];
        __syncwarp();

        // a-phase: j 0..15 u (kp 32..47), j 16..47 x (kp 64..95)
        u64t av0 = 0, av1 = 0;
        #pragma unroll
        for (int j = 0; j < 16; j++) MATA(32 + j, j);
        #pragma unroll
        for (int j = 16; j < 48; j++) MATA(48 + j, j);
        float a0 = f2_fold(av0), a1 = f2_fold(av1);

        // chain + interleaved w-independent MATXY ops:
        // ops {0..15 (u), 32..63 (x)} = 48 ops; 2/iter for iters 0..15, 1/iter after.
        u64t xA0 = 0, xA1 = 0, xB0 = 0, xB1 = 0;
        u64t yv0 = 0, yv1 = 0;
        #pragma unroll
        for (int i = 0; i < 16; i++) {
            CHAIN(i);
            { int m = 2 * i;     int op = (m < 16) ? m : m + 16; MATXY(op); }
            { int m = 2 * i + 1; int op = (m < 16) ? m : m + 16; MATXY(op); }
        }
        #pragma unroll
        for (int i = 16; i < 32; i++) { CHAIN(i); MATXY(i + 32); }

        // own w (a_lane final after iter=lane; later updates have zero coef)
        {
            float w0 = tanh_fast(a0), w1 = tanh_fast(a1);
            fS[idxw] = w0; fS[idxw + 2] = w1;
        }
        __syncwarp();

        // tail: w-part j16..31 (xn and y complete after this)
        #pragma unroll
        for (int j = 16; j < 32; j++) MATXY(j);
        fS[idxa] = f2_fold(xA0); fS[idxa + 2] = f2_fold(xA1);
        fS[idxb] = f2_fold(xB0); fS[idxb + 2] = f2_fold(xB1);
        yp0[t * 32] = f2_fold(yv0);
        yp1[t * 32] = f2_fold(yv1);

        uc0 = un0; uc1 = un1;
    }
}

// ---------------------------------------------------------------------------
extern "C" void kernel_launch(void* const* d_in, const int* in_sizes, int n_in,
                              void* d_out, int out_size) {
    const float* u_in  = (const float*)d_in[0];
    const float* x0    = (const float*)d_in[1];
    const float* X     = (const float*)d_in[2];
    const float* Y     = (const float*)d_in[3];
    const float* B2    = (const float*)d_in[4];
    const float* C2    = (const float*)d_in[5];
    const float* D12   = (const float*)d_in[6];
    const float* L     = (const float*)d_in[7];
    const float* U     = (const float*)d_in[8];
    const float* D21   = (const float*)d_in[9];
    const float* gamma = (const float*)d_in[10];
    float* y = (float*)d_out;

    const int setup_smem = 64 * 128 * 8 + 64 * 8 + 256;   // 66304 B dynamic
    const int main_smem  = (16384 + 8 * 384) * 4;         // 77824 B

    cudaFuncSetAttribute(ren_setup_a,  cudaFuncAttributeMaxDynamicSharedMemorySize, setup_smem);
    cudaFuncSetAttribute(ren_setup_cd, cudaFuncAttributeMaxDynamicSharedMemorySize, setup_smem);
    cudaFuncSetAttribute(ren_main,     cudaFuncAttributeMaxDynamicSharedMemorySize, main_smem);

    ren_setup_a<<<1, 256, setup_smem>>>(B2, C2, D12, L, U, D21, gamma);
    ren_setup_b<<<160, 256>>>(X, C2, D21);
    ren_setup_cd<<<64, 256, setup_smem>>>(Y, B2, C2, D12, D21);
    ren_main<<<128, 256, main_smem>>>(u_in, x0, y);
}

// round 12
// speedup vs baseline: 1.2336x; 1.2336x over previous
#include <cuda_runtime.h>
#include <math.h>

#define T_STEPS 256
typedef unsigned long long u64t;

struct Sc {
    float D22[32 * 32];
    float M[32 * 32];
    float Rinv[32 * 32];
    float vr[160 * 32];
    float T1[160 * 32];
    float H[160 * 160];
    float invLam[32];
};
__device__ Sc g_s;

// Weight image: WA 3072 | WX 8192 | WYF 4096 | DC 1024 = 16384 floats (64 KB)
#define OFF_WA 0
#define OFF_WX 3072
#define OFF_WY 11264
#define OFF_DC 15360
__device__ __align__(16) float g_params[16384];

__device__ __forceinline__ u64t f2_fma(u64t a, u64t b, u64t c) {
    u64t d; asm("fma.rn.f32x2 %0,%1,%2,%3;" : "=l"(d) : "l"(a), "l"(b), "l"(c)); return d;
}
__device__ __forceinline__ float f2_fold(u64t v) {
    float lo, hi; asm("mov.b64 {%0,%1},%2;" : "=f"(lo), "=f"(hi) : "l"(v));
    return lo + hi;
}
// tanh via ex2+rcp (abs err ~1e-7)
__device__ __forceinline__ float tanh_fast(float x) {
    float t = x * 2.885390081777926814f;
    float e; asm("ex2.approx.f32 %0,%1;" : "=f"(e) : "f"(t));
    float r; asm("rcp.approx.f32 %0,%1;" : "=f"(r) : "f"(e + 1.0f));
    return fmaf(-2.0f, r, 1.0f);
}

// ---------------- Gauss-Jordan (fp64, warp-parallel partial pivot) ----------------
__device__ void gj_invert(double* aug, int N, double* mv, int* s_piv, double* s_ipv) {
    const int tid = threadIdx.x, NT = blockDim.x;
    const int ld = 2 * N;
    for (int k = 0; k < N; k++) {
        if (tid < 32) {
            double best = -1.0; int bi = k;
            for (int r = k + tid; r < N; r += 32) {
                double v = fabs(aug[r * ld + k]);
                if (v > best) { best = v; bi = r; }
            }
            for (int o = 16; o; o >>= 1) {
                double ob = __shfl_down_sync(0xffffffffu, best, o);
                int    oi = __shfl_down_sync(0xffffffffu, bi, o);
                if (ob > best) { best = ob; bi = oi; }
            }
            if (tid == 0) *s_piv = bi;
        }
        __syncthreads();
        int p = *s_piv;
        if (p != k)
            for (int j = tid; j < ld; j += NT) {
                double tv = aug[k * ld + j];
                aug[k * ld + j] = aug[p * ld + j];
                aug[p * ld + j] = tv;
            }
        __syncthreads();
        if (tid == 0) *s_ipv = 1.0 / aug[k * ld + k];
        __syncthreads();
        double ipv = *s_ipv;
        for (int j = tid; j < ld; j += NT) aug[k * ld + j] *= ipv;
        __syncthreads();
        for (int r = tid; r < N; r += NT) mv[r] = aug[r * ld + k];
        __syncthreads();
        for (int idx = tid; idx < N * ld; idx += NT) {
            int r = idx / ld;
            if (r != k) {
                int j = idx - r * ld;
                aug[idx] -= mv[r] * aug[k * ld + j];
            }
        }
        __syncthreads();
    }
}

// ---------------- Setup A (1 block) ----------------
__global__ void ren_setup_a(const float* __restrict__ B2, const float* __restrict__ C2,
                            const float* __restrict__ D12, const float* __restrict__ L,
                            const float* __restrict__ U, const float* __restrict__ D21,
                            const float* __restrict__ gamma) {
    extern __shared__ double sd[];
    double* aug = sd;
    double* mv  = sd + 64 * 128;
    __shared__ int s_piv;
    __shared__ double s_ipv;
    const int tid = threadIdx.x, NT = blockDim.x;
    const float g = gamma[0];

    for (int idx = tid; idx < 1024; idx += NT) {
        int i = idx >> 5, j = idx & 31;
        float acc = (i == j) ? (g + 1.0f) : 0.0f;
        for (int k = 0; k < 32; k++) acc += L[k * 32 + i] * L[k * 32 + j];
        acc += U[i * 32 + j] - U[j * 32 + i];
        g_s.D22[idx] = acc;
    }
    __syncthreads();
    for (int idx = tid; idx < 32 * 64; idx += NT) {
        int i = idx >> 6, j = idx & 63;
        double v;
        if (j < 32) {
            float s = 0.0f;
            for (int k = 0; k < 32; k++) s += g_s.D22[k * 32 + i] * g_s.D22[k * 32 + j];
            v = (double)g_s.D22[i * 32 + j] + (double)g_s.D22[j * 32 + i] - 1e-4 * (double)s;
            if (i == j) v += -2.0 * (double)g;
        } else v = ((j - 32) == i) ? 1.0 : 0.0;
        aug[idx] = v;
    }
    __syncthreads();
    gj_invert(aug, 32, mv, &s_piv, &s_ipv);
    for (int idx = tid; idx < 1024; idx += NT) {
        int i = idx >> 5, j = idx & 31;
        g_s.Rinv[idx] = (float)aug[i * 64 + 32 + j];
    }
    for (int idx = tid; idx < 1024; idx += NT) {
        int i = idx >> 5, j = idx & 31;
        g_s.M[idx] = ((i == j) ? 1.0f : 0.0f) - 1e-4f * g_s.D22[j * 32 + i];
    }
    __syncthreads();
    for (int idx = tid; idx < 160 * 32; idx += NT) {
        int r = idx >> 5, c = idx & 31;
        float v;
        if (r < 64) {
            float s = 0.0f;
            for (int k = 0; k < 32; k++) s += g_s.M[c * 32 + k] * C2[k * 64 + r];
            v = s;
        } else if (r < 96) {
            int rr = r - 64;
            float s = 0.0f;
            for (int k = 0; k < 32; k++) s += g_s.M[c * 32 + k] * D21[k * 32 + rr];
            v = s - D12[rr * 32 + c];
        } else v = B2[(r - 96) * 32 + c];
        g_s.vr[idx] = v;
    }
    __syncthreads();
    for (int idx = tid; idx < 160 * 32; idx += NT) {
        int r = idx >> 5, c = idx & 31;
        float s = 0.0f;
        for (int k = 0; k < 32; k++) s += g_s.vr[r * 32 + k] * g_s.Rinv[k * 32 + c];
        g_s.T1[idx] = s;
    }
}

// ---------------- Setup B (160 blocks) ----------------
__global__ void ren_setup_b(const float* __restrict__ X, const float* __restrict__ C2,
                            const float* __restrict__ D21) {
    __shared__ float Xa[160];
    __shared__ float T1a[32];
    __shared__ float vqa[32];
    const int a = blockIdx.x;
    const int tid = threadIdx.x;
    for (int k = tid; k < 160; k += blockDim.x) Xa[k] = X[k * 160 + a];
    if (tid < 32) {
        T1a[tid] = g_s.T1[a * 32 + tid];
        float vq = 0.0f;
        if (a < 64) vq = C2[tid * 64 + a];
        else if (a < 96) vq = D21[tid * 32 + (a - 64)];
        vqa[tid] = vq;
    }
    __syncthreads();
    for (int b = tid; b < 160; b += blockDim.x) {
        float gsum = 0.0f;
        for (int k = 0; k < 160; k++) gsum += Xa[k] * X[k * 160 + b];
        float pr = 0.0f;
        for (int c = 0; c < 32; c++) pr += T1a[c] * g_s.vr[b * 32 + c];
        float q = 0.0f;
        if (b < 96)
            for (int c = 0; c < 32; c++) {
                float vb = (b < 64) ? C2[c * 64 + b] : D21[c * 32 + (b - 64)];
                q += vqa[c] * vb;
            }
        float h = gsum + pr + 1e-4f * q;
        if (a == b) h += 1e-3f;
        g_s.H[a * 160 + b] = h;
    }
}

// ---------------- Setup CD (64 blocks x 256) ----------------
// Each block assembles E, runs GJ64 locally, builds its 256-entry weight slice.
// WYF = y folded through xn. CE = C2 @ Einv precomputed cooperatively (R11 fix).
__global__ void ren_setup_cd(const float* __restrict__ Y, const float* __restrict__ B2,
                             const float* __restrict__ C2, const float* __restrict__ D12,
                             const float* __restrict__ D21) {
    extern __shared__ double sd[];
    double* aug = sd;
    double* mv  = sd + 64 * 128;
    __shared__ int s_piv;
    __shared__ double s_ipv;
    __shared__ float CE[32 * 64];   // C2 @ Einv
    const int tid = threadIdx.x, NT = blockDim.x;

    for (int idx = tid; idx < 64 * 128; idx += NT) {
        int i = idx >> 7, j = idx & 127;
        double v;
        if (j < 64)
            v = 0.5 * ((double)g_s.H[i * 160 + j] + (double)g_s.H[(96 + i) * 160 + (96 + j)]
                       + (double)Y[i * 64 + j] - (double)Y[j * 64 + i]);
        else v = ((j - 64) == i) ? 1.0 : 0.0;
        aug[idx] = v;
    }
    __syncthreads();
    gj_invert(aug, 64, mv, &s_piv, &s_ipv);

#define EINV(r, c) ((float)aug[(r) * 128 + 64 + (c)])
    // CE[i][n] = sum_m C2[i][m] * Einv[m][n]
    for (int idx = tid; idx < 32 * 64; idx += NT) {
        int i = idx >> 6, n = idx & 63;
        float s = 0.0f;
        for (int m = 0; m < 64; m++) s += C2[i * 64 + m] * EINV(m, n);
        CE[idx] = s;
    }
    __syncthreads();

    const int g = blockIdx.x * 256 + tid;   // 0..16383
    if (g < 8192) {
        // WX: float4[j*32+lane] = (rowA c0, rowA c1, rowB c0, rowB c1)
        int e = g;
        int comp = e & 3, r = e >> 2, j = r >> 5, lane = r & 31;
        int row = (comp < 2) ? lane : lane + 32;
        int c = comp & 1;
        float s = 0.0f;
        if (j < 16) {
            int col = 2 * j + c;
            for (int m = 0; m < 64; m++) s += EINV(row, m) * B2[m * 32 + col];
        } else if (j < 32) {
            int col = 2 * (j - 16) + c;
            for (int m = 0; m < 64; m++) s += EINV(row, m) * g_s.H[(96 + m) * 160 + 64 + col];
        } else {
            int col = 2 * (j - 32) + c;
            for (int m = 0; m < 64; m++) s += EINV(row, m) * g_s.H[(96 + m) * 160 + col];
        }
        g_params[OFF_WX + e] = s;
    } else if (g < 11264) {
        // WA: float2[j*32+i]; j<16 u (D12), else x (C1=-H21); * invLam[i]
        int e = g - 8192;
        int c = e & 1, r = e >> 1, j = r >> 5, i = r & 31;
        float invLam = 1.0f / (0.5f * g_s.H[(64 + i) * 160 + (64 + i)]);
        float v;
        if (j < 16) v = D12[i * 32 + 2 * j + c];
        else        v = -g_s.H[(64 + i) * 160 + 2 * (j - 16) + c];
        g_params[OFF_WA + e] = v * invLam;
    } else if (g < 15360) {
        // WYF: float2[j*32+i]; j<16 u: CE@B2 + D22; j<32 w: CE@H32 + D21;
        //                      j>=32 x: CE@H31
        int e = g - 11264;
        int c = e & 1, r = e >> 1, j = r >> 5, i = r & 31;
        int col;
        float val;
        if (j < 16)      { col = 2 * j + c;        val = g_s.D22[i * 32 + col]; }
        else if (j < 32) { col = 2 * (j - 16) + c; val = D21[i * 32 + col]; }
        else             { col = 2 * (j - 32) + c; val = 0.0f; }
        float acc = 0.0f;
        for (int n = 0; n < 64; n++) {
            float sv;
            if (j < 16)      sv = B2[n * 32 + col];
            else if (j < 32) sv = g_s.H[(96 + n) * 160 + 64 + col];
            else             sv = g_s.H[(96 + n) * 160 + col];
            acc += CE[i * 64 + n] * sv;
        }
        g_params[OFF_WY + e] = val + acc;
    } else {
        // DC: float[i*32+l] = (l>i) ? -H22[l][i]/Lam[l] : 0
        int e = g - 15360;
        int i = e >> 5, l = e & 31;
        float invLam = 1.0f / (0.5f * g_s.H[(64 + l) * 160 + (64 + l)]);
        g_params[OFF_DC + e] =
            (l > i) ? (-g_s.H[(64 + l) * 160 + (64 + i)] * invLam) : 0.0f;
    }
#undef EINV
}

// ---------------------------------------------------------------------------
// Main: R10's ren_main VERBATIM (measured 955 us): E=2, 8 warps, 128 blocks,
// y folded into x-phase (MATXY), wa_r + dc_r register-cached.
// ---------------------------------------------------------------------------
__global__ void __launch_bounds__(256, 1)
ren_main(const float* __restrict__ u_in, const float* __restrict__ x0,
         float* __restrict__ y_out) {
    extern __shared__ float sm[];
    {
        float4* dst = (float4*)sm;
        const float4* src = (const float4*)g_params;
        for (int i = threadIdx.x; i < 4096; i += blockDim.x) dst[i] = src[i];
    }
    const int warp = threadIdx.x >> 5;
    const int lane = threadIdx.x & 31;
    float* fS = sm + 16384 + warp * 384;
    const float4* SA = (const float4*)fS;
    __syncthreads();

    // register-cached weights
    u64t wa_r[48];
    #pragma unroll
    for (int j = 0; j < 48; j++)
        wa_r[j] = *(const u64t*)(sm + OFF_WA + (j * 32 + lane) * 2);
    float dc_r[32];
    #pragma unroll
    for (int i = 0; i < 32; i++)
        dc_r[i] = sm[OFF_DC + i * 32 + lane];

    const int e0 = (blockIdx.x * 8 + warp) * 2;
    const float* up0 = u_in + (size_t)(e0 + 0) * (T_STEPS * 32);
    const float* up1 = u_in + (size_t)(e0 + 1) * (T_STEPS * 32);
    float* yp0 = y_out + (size_t)(e0 + 0) * (T_STEPS * 32) + lane;
    float* yp1 = y_out + (size_t)(e0 + 1) * (T_STEPS * 32) + lane;

    // init x state (kp 64..95)
    {
        int ia = (64 + (lane >> 1)) * 4 + (lane & 1);
        int ib = (80 + (lane >> 1)) * 4 + (lane & 1);
        fS[ia]     = x0[(e0 + 0) * 64 + lane];
        fS[ia + 2] = x0[(e0 + 1) * 64 + lane];
        fS[ib]     = x0[(e0 + 0) * 64 + 32 + lane];
        fS[ib + 2] = x0[(e0 + 1) * 64 + 32 + lane];
    }
    float uc0 = up0[lane], uc1 = up1[lane];

    const int idxu = (32 + (lane >> 1)) * 4 + (lane & 1);
    const int idxw = (48 + (lane >> 1)) * 4 + (lane & 1);
    const int idxa = (64 + (lane >> 1)) * 4 + (lane & 1);
    const int idxb = (80 + (lane >> 1)) * 4 + (lane & 1);

#define LD2(p)  (*(const ulonglong2*)(p))
// a-phase state map: j<16 -> u at kp 32+j; j>=16 -> x at kp 48+j (=64..95)
#define MATA(kp, j) { \
    ulonglong2 s = LD2(SA + (kp)); \
    av0 = f2_fma(wa_r[j], s.x, av0); av1 = f2_fma(wa_r[j], s.y, av1); }
// combined x+y op: one state load feeds xn rowA, xn rowB, y row
#define MATXY(j) { \
    ulonglong2 wv = *(const ulonglong2*)(sm + OFF_WX + ((j) * 32 + lane) * 4); \
    u64t wy = *(const u64t*)(sm + OFF_WY + ((j) * 32 + lane) * 2); \
    ulonglong2 s  = LD2(SA + 32 + (j)); \
    xA0 = f2_fma(wv.x, s.x, xA0); xA1 = f2_fma(wv.x, s.y, xA1); \
    xB0 = f2_fma(wv.y, s.x, xB0); xB1 = f2_fma(wv.y, s.y, xB1); \
    yv0 = f2_fma(wy, s.x, yv0); yv1 = f2_fma(wy, s.y, yv1); }
#define CHAIN(i) { \
    float t0 = tanh_fast(a0), t1 = tanh_fast(a1); \
    t0 = __shfl_sync(0xffffffffu, t0, (i)); t1 = __shfl_sync(0xffffffffu, t1, (i)); \
    float d = dc_r[i]; \
    a0 = fmaf(d, t0, a0); a1 = fmaf(d, t1, a1); }

    for (int t = 0; t < T_STEPS; t++) {
        fS[idxu] = uc0; fS[idxu + 2] = uc1;
        int tn = (t < T_STEPS - 1) ? (t + 1) : t;
        float un0 = up0[tn * 32 + lane], un1 = up1[tn * 32 + lane];
        __syncwarp();

        // a-phase: j 0..15 u (kp 32..47), j 16..47 x (kp 64..95)
        u64t av0 = 0, av1 = 0;
        #pragma unroll
        for (int j = 0; j < 16; j++) MATA(32 + j, j);
        #pragma unroll
        for (int j = 16; j < 48; j++) MATA(48 + j, j);
        float a0 = f2_fold(av0), a1 = f2_fold(av1);

        // chain + interleaved w-independent MATXY ops:
        // ops {0..15 (u), 32..63 (x)} = 48 ops; 2/iter for iters 0..15, 1/iter after.
        u64t xA0 = 0, xA1 = 0, xB0 = 0, xB1 = 0;
        u64t yv0 = 0, yv1 = 0;
        #pragma unroll
        for (int i = 0; i < 16; i++) {
            CHAIN(i);
            { int m = 2 * i;     int op = (m < 16) ? m : m + 16; MATXY(op); }
            { int m = 2 * i + 1; int op = (m < 16) ? m : m + 16; MATXY(op); }
        }
        #pragma unroll
        for (int i = 16; i < 32; i++) { CHAIN(i); MATXY(i + 32); }

        // own w (a_lane final after iter=lane; later updates have zero coef)
        {
            float w0 = tanh_fast(a0), w1 = tanh_fast(a1);
            fS[idxw] = w0; fS[idxw + 2] = w1;
        }
        __syncwarp();

        // tail: w-part j16..31 (xn and y complete after this)
        #pragma unroll
        for (int j = 16; j < 32; j++) MATXY(j);
        fS[idxa] = f2_fold(xA0); fS[idxa + 2] = f2_fold(xA1);
        fS[idxb] = f2_fold(xB0); fS[idxb + 2] = f2_fold(xB1);
        yp0[t * 32] = f2_fold(yv0);
        yp1[t * 32] = f2_fold(yv1);

        uc0 = un0; uc1 = un1;
    }
}

// ---------------------------------------------------------------------------
extern "C" void kernel_launch(void* const* d_in, const int* in_sizes, int n_in,
                              void* d_out, int out_size) {
    const float* u_in  = (const float*)d_in[0];
    const float* x0    = (const float*)d_in[1];
    const float* X     = (const float*)d_in[2];
    const float* Y     = (const float*)d_in[3];
    const float* B2    = (const float*)d_in[4];
    const float* C2    = (const float*)d_in[5];
    const float* D12   = (const float*)d_in[6];
    const float* L     = (const float*)d_in[7];
    const float* U     = (const float*)d_in[8];
    const float* D21   = (const float*)d_in[9];
    const float* gamma = (const float*)d_in[10];
    float* y = (float*)d_out;

    const int setup_smem = 64 * 128 * 8 + 64 * 8 + 256;   // 66304 B dynamic
    const int main_smem  = (16384 + 8 * 384) * 4;         // 77824 B

    cudaFuncSetAttribute(ren_setup_a,  cudaFuncAttributeMaxDynamicSharedMemorySize, setup_smem);
    cudaFuncSetAttribute(ren_setup_cd, cudaFuncAttributeMaxDynamicSharedMemorySize, setup_smem);
    cudaFuncSetAttribute(ren_main,     cudaFuncAttributeMaxDynamicSharedMemorySize, main_smem);

    ren_setup_a<<<1, 256, setup_smem>>>(B2, C2, D12, L, U, D21, gamma);
    ren_setup_b<<<160, 256>>>(X, C2, D21);
    ren_setup_cd<<<64, 256, setup_smem>>>(Y, B2, C2, D12, D21);
    ren_main<<<128, 256, main_smem>>>(u_in, x0, y);
}

// round 13
// speedup vs baseline: 1.4524x; 1.1774x over previous
#include <cuda_runtime.h>
#include <math.h>

#define T_STEPS 256
typedef unsigned long long u64t;

struct Sc {
    float D22[32 * 32];
    float M[32 * 32];
    float Rinv[32 * 32];
    float vr[160 * 32];
    float T1[160 * 32];
    float H[160 * 160];
    float invLam[32];
};
__device__ Sc g_s;

// Weight image: WA 3072 | WX 8192 | WYF 4096 | DC 1024 = 16384 floats (64 KB)
#define OFF_WA 0
#define OFF_WX 3072
#define OFF_WY 11264
#define OFF_DC 15360
__device__ __align__(16) float g_params[16384];

__device__ __forceinline__ u64t f2_fma(u64t a, u64t b, u64t c) {
    u64t d; asm("fma.rn.f32x2 %0,%1,%2,%3;" : "=l"(d) : "l"(a), "l"(b), "l"(c)); return d;
}
__device__ __forceinline__ float f2_fold(u64t v) {
    float lo, hi; asm("mov.b64 {%0,%1},%2;" : "=f"(lo), "=f"(hi) : "l"(v));
    return lo + hi;
}
// tanh via ex2+rcp (abs err ~1e-7)
__device__ __forceinline__ float tanh_fast(float x) {
    float t = x * 2.885390081777926814f;
    float e; asm("ex2.approx.f32 %0,%1;" : "=f"(e) : "f"(t));
    float r; asm("rcp.approx.f32 %0,%1;" : "=f"(r) : "f"(e + 1.0f));
    return fmaf(-2.0f, r, 1.0f);
}

// ---------------- Gauss-Jordan (fp32, warp-parallel partial pivot) ----------------
// Reference computes jnp.linalg.inv in float32; fp32 GJ with partial pivoting is
// the same accuracy class and ~4-8x faster than fp64 on B300 (DFMA budget ~18/SM).
__device__ void gj_invert_f32(float* aug, int N, float* mv, int* s_piv, float* s_ipv) {
    const int tid = threadIdx.x, NT = blockDim.x;
    const int ld = 2 * N;
    for (int k = 0; k < N; k++) {
        if (tid < 32) {
            float best = -1.0f; int bi = k;
            for (int r = k + tid; r < N; r += 32) {
                float v = fabsf(aug[r * ld + k]);
                if (v > best) { best = v; bi = r; }
            }
            for (int o = 16; o; o >>= 1) {
                float ob = __shfl_down_sync(0xffffffffu, best, o);
                int   oi = __shfl_down_sync(0xffffffffu, bi, o);
                if (ob > best) { best = ob; bi = oi; }
            }
            if (tid == 0) *s_piv = bi;
        }
        __syncthreads();
        int p = *s_piv;
        if (p != k)
            for (int j = tid; j < ld; j += NT) {
                float tv = aug[k * ld + j];
                aug[k * ld + j] = aug[p * ld + j];
                aug[p * ld + j] = tv;
            }
        __syncthreads();
        if (tid == 0) *s_ipv = 1.0f / aug[k * ld + k];
        __syncthreads();
        float ipv = *s_ipv;
        for (int j = tid; j < ld; j += NT) aug[k * ld + j] *= ipv;
        __syncthreads();
        for (int r = tid; r < N; r += NT) mv[r] = aug[r * ld + k];
        __syncthreads();
        for (int idx = tid; idx < N * ld; idx += NT) {
            int r = idx / ld;
            if (r != k) {
                int j = idx - r * ld;
                aug[idx] -= mv[r] * aug[k * ld + j];
            }
        }
        __syncthreads();
    }
}

// ---------------- Setup A (1 block x 256) ----------------
__global__ void ren_setup_a(const float* __restrict__ B2, const float* __restrict__ C2,
                            const float* __restrict__ D12, const float* __restrict__ L,
                            const float* __restrict__ U, const float* __restrict__ D21,
                            const float* __restrict__ gamma) {
    extern __shared__ float sf[];
    float* aug = sf;                 // 32 x 64
    float* mv  = sf + 32 * 64;       // 32
    __shared__ int s_piv;
    __shared__ float s_ipv;
    const int tid = threadIdx.x, NT = blockDim.x;
    const float g = gamma[0];

    for (int idx = tid; idx < 1024; idx += NT) {
        int i = idx >> 5, j = idx & 31;
        float acc = (i == j) ? (g + 1.0f) : 0.0f;
        for (int k = 0; k < 32; k++) acc += L[k * 32 + i] * L[k * 32 + j];
        acc += U[i * 32 + j] - U[j * 32 + i];
        g_s.D22[idx] = acc;
    }
    __syncthreads();
    for (int idx = tid; idx < 32 * 64; idx += NT) {
        int i = idx >> 6, j = idx & 63;
        float v;
        if (j < 32) {
            float s = 0.0f;
            for (int k = 0; k < 32; k++) s += g_s.D22[k * 32 + i] * g_s.D22[k * 32 + j];
            v = g_s.D22[i * 32 + j] + g_s.D22[j * 32 + i] - 1e-4f * s;
            if (i == j) v += -2.0f * g;
        } else v = ((j - 32) == i) ? 1.0f : 0.0f;
        aug[idx] = v;
    }
    __syncthreads();
    gj_invert_f32(aug, 32, mv, &s_piv, &s_ipv);
    for (int idx = tid; idx < 1024; idx += NT) {
        int i = idx >> 5, j = idx & 31;
        g_s.Rinv[idx] = aug[i * 64 + 32 + j];
    }
    for (int idx = tid; idx < 1024; idx += NT) {
        int i = idx >> 5, j = idx & 31;
        g_s.M[idx] = ((i == j) ? 1.0f : 0.0f) - 1e-4f * g_s.D22[j * 32 + i];
    }
    __syncthreads();
    for (int idx = tid; idx < 160 * 32; idx += NT) {
        int r = idx >> 5, c = idx & 31;
        float v;
        if (r < 64) {
            float s = 0.0f;
            for (int k = 0; k < 32; k++) s += g_s.M[c * 32 + k] * C2[k * 64 + r];
            v = s;
        } else if (r < 96) {
            int rr = r - 64;
            float s = 0.0f;
            for (int k = 0; k < 32; k++) s += g_s.M[c * 32 + k] * D21[k * 32 + rr];
            v = s - D12[rr * 32 + c];
        } else v = B2[(r - 96) * 32 + c];
        g_s.vr[idx] = v;
    }
    __syncthreads();
    for (int idx = tid; idx < 160 * 32; idx += NT) {
        int r = idx >> 5, c = idx & 31;
        float s = 0.0f;
        for (int k = 0; k < 32; k++) s += g_s.vr[r * 32 + k] * g_s.Rinv[k * 32 + c];
        g_s.T1[idx] = s;
    }
}

// ---------------- Setup B (160 blocks) ----------------
__global__ void ren_setup_b(const float* __restrict__ X, const float* __restrict__ C2,
                            const float* __restrict__ D21) {
    __shared__ float Xa[160];
    __shared__ float T1a[32];
    __shared__ float vqa[32];
    const int a = blockIdx.x;
    const int tid = threadIdx.x;
    for (int k = tid; k < 160; k += blockDim.x) Xa[k] = X[k * 160 + a];
    if (tid < 32) {
        T1a[tid] = g_s.T1[a * 32 + tid];
        float vq = 0.0f;
        if (a < 64) vq = C2[tid * 64 + a];
        else if (a < 96) vq = D21[tid * 32 + (a - 64)];
        vqa[tid] = vq;
    }
    __syncthreads();
    for (int b = tid; b < 160; b += blockDim.x) {
        float gsum = 0.0f;
        for (int k = 0; k < 160; k++) gsum += Xa[k] * X[k * 160 + b];
        float pr = 0.0f;
        for (int c = 0; c < 32; c++) pr += T1a[c] * g_s.vr[b * 32 + c];
        float q = 0.0f;
        if (b < 96)
            for (int c = 0; c < 32; c++) {
                float vb = (b < 64) ? C2[c * 64 + b] : D21[c * 32 + (b - 64)];
                q += vqa[c] * vb;
            }
        float h = gsum + pr + 1e-4f * q;
        if (a == b) h += 1e-3f;
        g_s.H[a * 160 + b] = h;
    }
}

// ---------------- Setup CD (32 blocks x 512) ----------------
// Each block assembles E (fp32), runs GJ64 locally, builds its 512-entry slice.
// WYF = y folded through xn. CE = C2 @ Einv precomputed cooperatively.
__global__ void ren_setup_cd(const float* __restrict__ Y, const float* __restrict__ B2,
                             const float* __restrict__ C2, const float* __restrict__ D12,
                             const float* __restrict__ D21) {
    extern __shared__ float sf[];
    float* aug = sf;                 // 64 x 128
    float* mv  = sf + 64 * 128;      // 64
    __shared__ int s_piv;
    __shared__ float s_ipv;
    __shared__ float CE[32 * 64];    // C2 @ Einv
    const int tid = threadIdx.x, NT = blockDim.x;

    for (int idx = tid; idx < 64 * 128; idx += NT) {
        int i = idx >> 7, j = idx & 127;
        float v;
        if (j < 64)
            v = 0.5f * (g_s.H[i * 160 + j] + g_s.H[(96 + i) * 160 + (96 + j)]
                        + Y[i * 64 + j] - Y[j * 64 + i]);
        else v = ((j - 64) == i) ? 1.0f : 0.0f;
        aug[idx] = v;
    }
    __syncthreads();
    gj_invert_f32(aug, 64, mv, &s_piv, &s_ipv);

#define EINV(r, c) (aug[(r) * 128 + 64 + (c)])
    // CE[i][n] = sum_m C2[i][m] * Einv[m][n]
    for (int idx = tid; idx < 32 * 64; idx += NT) {
        int i = idx >> 6, n = idx & 63;
        float s = 0.0f;
        for (int m = 0; m < 64; m++) s += C2[i * 64 + m] * EINV(m, n);
        CE[idx] = s;
    }
    __syncthreads();

    const int g = blockIdx.x * 512 + tid;   // 0..16383 (32 blocks x 512 threads)
    if (g < 8192) {
        // WX: float4[j*32+lane] = (rowA c0, rowA c1, rowB c0, rowB c1)
        int e = g;
        int comp = e & 3, r = e >> 2, j = r >> 5, lane = r & 31;
        int row = (comp < 2) ? lane : lane + 32;
        int c = comp & 1;
        float s = 0.0f;
        if (j < 16) {
            int col = 2 * j + c;
            for (int m = 0; m < 64; m++) s += EINV(row, m) * B2[m * 32 + col];
        } else if (j < 32) {
            int col = 2 * (j - 16) + c;
            for (int m = 0; m < 64; m++) s += EINV(row, m) * g_s.H[(96 + m) * 160 + 64 + col];
        } else {
            int col = 2 * (j - 32) + c;
            for (int m = 0; m < 64; m++) s += EINV(row, m) * g_s.H[(96 + m) * 160 + col];
        }
        g_params[OFF_WX + e] = s;
    } else if (g < 11264) {
        // WA: float2[j*32+i]; j<16 u (D12), else x (C1=-H21); * invLam[i]
        int e = g - 8192;
        int c = e & 1, r = e >> 1, j = r >> 5, i = r & 31;
        float invLam = 1.0f / (0.5f * g_s.H[(64 + i) * 160 + (64 + i)]);
        float v;
        if (j < 16) v = D12[i * 32 + 2 * j + c];
        else        v = -g_s.H[(64 + i) * 160 + 2 * (j - 16) + c];
        g_params[OFF_WA + e] = v * invLam;
    } else if (g < 15360) {
        // WYF: float2[j*32+i]; j<16 u: CE@B2 + D22; j<32 w: CE@H32 + D21;
        //                      j>=32 x: CE@H31
        int e = g - 11264;
        int c = e & 1, r = e >> 1, j = r >> 5, i = r & 31;
        int col;
        float val;
        if (j < 16)      { col = 2 * j + c;        val = g_s.D22[i * 32 + col]; }
        else if (j < 32) { col = 2 * (j - 16) + c; val = D21[i * 32 + col]; }
        else             { col = 2 * (j - 32) + c; val = 0.0f; }
        float acc = 0.0f;
        for (int n = 0; n < 64; n++) {
            float sv;
            if (j < 16)      sv = B2[n * 32 + col];
            else if (j < 32) sv = g_s.H[(96 + n) * 160 + 64 + col];
            else             sv = g_s.H[(96 + n) * 160 + col];
            acc += CE[i * 64 + n] * sv;
        }
        g_params[OFF_WY + e] = val + acc;
    } else {
        // DC: float[i*32+l] = (l>i) ? -H22[l][i]/Lam[l] : 0
        int e = g - 15360;
        int i = e >> 5, l = e & 31;
        float invLam = 1.0f / (0.5f * g_s.H[(64 + l) * 160 + (64 + l)]);
        g_params[OFF_DC + e] =
            (l > i) ? (-g_s.H[(64 + l) * 160 + (64 + i)] * invLam) : 0.0f;
    }
#undef EINV
}

// ---------------------------------------------------------------------------
// Main: R12's ren_main VERBATIM (measured 955-981 us): E=2, 8 warps, 128
// blocks, y folded into x-phase (MATXY), wa_r + dc_r register-cached.
// ---------------------------------------------------------------------------
__global__ void __launch_bounds__(256, 1)
ren_main(const float* __restrict__ u_in, const float* __restrict__ x0,
         float* __restrict__ y_out) {
    extern __shared__ float sm[];
    {
        float4* dst = (float4*)sm;
        const float4* src = (const float4*)g_params;
        for (int i = threadIdx.x; i < 4096; i += blockDim.x) dst[i] = src[i];
    }
    const int warp = threadIdx.x >> 5;
    const int lane = threadIdx.x & 31;
    float* fS = sm + 16384 + warp * 384;
    const float4* SA = (const float4*)fS;
    __syncthreads();

    // register-cached weights
    u64t wa_r[48];
    #pragma unroll
    for (int j = 0; j < 48; j++)
        wa_r[j] = *(const u64t*)(sm + OFF_WA + (j * 32 + lane) * 2);
    float dc_r[32];
    #pragma unroll
    for (int i = 0; i < 32; i++)
        dc_r[i] = sm[OFF_DC + i * 32 + lane];

    const int e0 = (blockIdx.x * 8 + warp) * 2;
    const float* up0 = u_in + (size_t)(e0 + 0) * (T_STEPS * 32);
    const float* up1 = u_in + (size_t)(e0 + 1) * (T_STEPS * 32);
    float* yp0 = y_out + (size_t)(e0 + 0) * (T_STEPS * 32) + lane;
    float* yp1 = y_out + (size_t)(e0 + 1) * (T_STEPS * 32) + lane;

    // init x state (kp 64..95)
    {
        int ia = (64 + (lane >> 1)) * 4 + (lane & 1);
        int ib = (80 + (lane >> 1)) * 4 + (lane & 1);
        fS[ia]     = x0[(e0 + 0) * 64 + lane];
        fS[ia + 2] = x0[(e0 + 1) * 64 + lane];
        fS[ib]     = x0[(e0 + 0) * 64 + 32 + lane];
        fS[ib + 2] = x0[(e0 + 1) * 64 + 32 + lane];
    }
    float uc0 = up0[lane], uc1 = up1[lane];

    const int idxu = (32 + (lane >> 1)) * 4 + (lane & 1);
    const int idxw = (48 + (lane >> 1)) * 4 + (lane & 1);
    const int idxa = (64 + (lane >> 1)) * 4 + (lane & 1);
    const int idxb = (80 + (lane >> 1)) * 4 + (lane & 1);

#define LD2(p)  (*(const ulonglong2*)(p))
// a-phase state map: j<16 -> u at kp 32+j; j>=16 -> x at kp 48+j (=64..95)
#define MATA(kp, j) { \
    ulonglong2 s = LD2(SA + (kp)); \
    av0 = f2_fma(wa_r[j], s.x, av0); av1 = f2_fma(wa_r[j], s.y, av1); }
// combined x+y op: one state load feeds xn rowA, xn rowB, y row
#define MATXY(j) { \
    ulonglong2 wv = *(const ulonglong2*)(sm + OFF_WX + ((j) * 32 + lane) * 4); \
    u64t wy = *(const u64t*)(sm + OFF_WY + ((j) * 32 + lane) * 2); \
    ulonglong2 s  = LD2(SA + 32 + (j)); \
    xA0 = f2_fma(wv.x, s.x, xA0); xA1 = f2_fma(wv.x, s.y, xA1); \
    xB0 = f2_fma(wv.y, s.x, xB0); xB1 = f2_fma(wv.y, s.y, xB1); \
    yv0 = f2_fma(wy, s.x, yv0); yv1 = f2_fma(wy, s.y, yv1); }
#define CHAIN(i) { \
    float t0 = tanh_fast(a0), t1 = tanh_fast(a1); \
    t0 = __shfl_sync(0xffffffffu, t0, (i)); t1 = __shfl_sync(0xffffffffu, t1, (i)); \
    float d = dc_r[i]; \
    a0 = fmaf(d, t0, a0); a1 = fmaf(d, t1, a1); }

    for (int t = 0; t < T_STEPS; t++) {
        fS[idxu] = uc0; fS[idxu + 2] = uc1;
        int tn = (t < T_STEPS - 1) ? (t + 1) : t;
        float un0 = up0[tn * 32 + lane], un1 = up1[tn * 32 + lane];
        __syncwarp();

        // a-phase: j 0..15 u (kp 32..47), j 16..47 x (kp 64..95)
        u64t av0 = 0, av1 = 0;
        #pragma unroll
        for (int j = 0; j < 16; j++) MATA(32 + j, j);
        #pragma unroll
        for (int j = 16; j < 48; j++) MATA(48 + j, j);
        float a0 = f2_fold(av0), a1 = f2_fold(av1);

        // chain + interleaved w-independent MATXY ops:
        // ops {0..15 (u), 32..63 (x)} = 48 ops; 2/iter for iters 0..15, 1/iter after.
        u64t xA0 = 0, xA1 = 0, xB0 = 0, xB1 = 0;
        u64t yv0 = 0, yv1 = 0;
        #pragma unroll
        for (int i = 0; i < 16; i++) {
            CHAIN(i);
            { int m = 2 * i;     int op = (m < 16) ? m : m + 16; MATXY(op); }
            { int m = 2 * i + 1; int op = (m < 16) ? m : m + 16; MATXY(op); }
        }
        #pragma unroll
        for (int i = 16; i < 32; i++) { CHAIN(i); MATXY(i + 32); }

        // own w (a_lane final after iter=lane; later updates have zero coef)
        {
            float w0 = tanh_fast(a0), w1 = tanh_fast(a1);
            fS[idxw] = w0; fS[idxw + 2] = w1;
        }
        __syncwarp();

        // tail: w-part j16..31 (xn and y complete after this)
        #pragma unroll
        for (int j = 16; j < 32; j++) MATXY(j);
        fS[idxa] = f2_fold(xA0); fS[idxa + 2] = f2_fold(xA1);
        fS[idxb] = f2_fold(xB0); fS[idxb + 2] = f2_fold(xB1);
        yp0[t * 32] = f2_fold(yv0);
        yp1[t * 32] = f2_fold(yv1);

        uc0 = un0; uc1 = un1;
    }
}

// ---------------------------------------------------------------------------
extern "C" void kernel_launch(void* const* d_in, const int* in_sizes, int n_in,
                              void* d_out, int out_size) {
    const float* u_in  = (const float*)d_in[0];
    const float* x0    = (const float*)d_in[1];
    const float* X     = (const float*)d_in[2];
    const float* Y     = (const float*)d_in[3];
    const float* B2    = (const float*)d_in[4];
    const float* C2    = (const float*)d_in[5];
    const float* D12   = (const float*)d_in[6];
    const float* L     = (const float*)d_in[7];
    const float* U     = (const float*)d_in[8];
    const float* D21   = (const float*)d_in[9];
    const float* gamma = (const float*)d_in[10];
    float* y = (float*)d_out;

    const int setup_smem = 64 * 128 * 4 + 64 * 4 + 256;   // 33280 B (fp32 aug + mv)
    const int main_smem  = (16384 + 8 * 384) * 4;         // 77824 B

    cudaFuncSetAttribute(ren_setup_a,  cudaFuncAttributeMaxDynamicSharedMemorySize, setup_smem);
    cudaFuncSetAttribute(ren_setup_cd, cudaFuncAttributeMaxDynamicSharedMemorySize, setup_smem);
    cudaFuncSetAttribute(ren_main,     cudaFuncAttributeMaxDynamicSharedMemorySize, main_smem);

    ren_setup_a<<<1, 256, setup_smem>>>(B2, C2, D12, L, U, D21, gamma);
    ren_setup_b<<<160, 256>>>(X, C2, D21);
    ren_setup_cd<<<32, 512, setup_smem>>>(Y, B2, C2, D12, D21);
    ren_main<<<128, 256, main_smem>>>(u_in, x0, y);
}

// round 14
// speedup vs baseline: 1.5206x; 1.0470x over previous
#include <cuda_runtime.h>
#include <math.h>

#define T_STEPS 256
typedef unsigned long long u64t;

struct Sc {
    float D22[32 * 32];
    float vr[160 * 32];
    float T1[160 * 32];
    float H[160 * 160];
};
__device__ Sc g_s;

// Weight image: WA 3072 | WX 8192 | WYF 4096 | DC 1024 = 16384 floats (64 KB)
#define OFF_WA 0
#define OFF_WX 3072
#define OFF_WY 11264
#define OFF_DC 15360
__device__ __align__(16) float g_params[16384];

__device__ __forceinline__ u64t f2_fma(u64t a, u64t b, u64t c) {
    u64t d; asm("fma.rn.f32x2 %0,%1,%2,%3;" : "=l"(d) : "l"(a), "l"(b), "l"(c)); return d;
}
__device__ __forceinline__ float f2_fold(u64t v) {
    float lo, hi; asm("mov.b64 {%0,%1},%2;" : "=f"(lo), "=f"(hi) : "l"(v));
    return lo + hi;
}
// tanh via ex2+rcp (abs err ~1e-7)
__device__ __forceinline__ float tanh_fast(float x) {
    float t = x * 2.885390081777926814f;
    float e; asm("ex2.approx.f32 %0,%1;" : "=f"(e) : "f"(t));
    float r; asm("rcp.approx.f32 %0,%1;" : "=f"(r) : "f"(e + 1.0f));
    return fmaf(-2.0f, r, 1.0f);
}

// ---------------- Gauss-Jordan (fp32, warp-parallel partial pivot) ----------------
__device__ void gj_invert_f32(float* aug, int N, float* mv, int* s_piv, float* s_ipv) {
    const int tid = threadIdx.x, NT = blockDim.x;
    const int ld = 2 * N;
    for (int k = 0; k < N; k++) {
        if (tid < 32) {
            float best = -1.0f; int bi = k;
            for (int r = k + tid; r < N; r += 32) {
                float v = fabsf(aug[r * ld + k]);
                if (v > best) { best = v; bi = r; }
            }
            for (int o = 16; o; o >>= 1) {
                float ob = __shfl_down_sync(0xffffffffu, best, o);
                int   oi = __shfl_down_sync(0xffffffffu, bi, o);
                if (ob > best) { best = ob; bi = oi; }
            }
            if (tid == 0) *s_piv = bi;
        }
        __syncthreads();
        int p = *s_piv;
        if (p != k)
            for (int j = tid; j < ld; j += NT) {
                float tv = aug[k * ld + j];
                aug[k * ld + j] = aug[p * ld + j];
                aug[p * ld + j] = tv;
            }
        __syncthreads();
        if (tid == 0) *s_ipv = 1.0f / aug[k * ld + k];
        __syncthreads();
        float ipv = *s_ipv;
        for (int j = tid; j < ld; j += NT) aug[k * ld + j] *= ipv;
        __syncthreads();
        for (int r = tid; r < N; r += NT) mv[r] = aug[r * ld + k];
        __syncthreads();
        for (int idx = tid; idx < N * ld; idx += NT) {
            int r = idx / ld;
            if (r != k) {
                int j = idx - r * ld;
                aug[idx] -= mv[r] * aug[k * ld + j];
            }
        }
        __syncthreads();
    }
}

// ---------------- Setup A (1 block x 256) — ALL-SMEM version ----------------
// Stages every input and intermediate in shared memory; gmem touched only for
// the final D22 / vr / T1 writes consumed by setup_b / setup_cd.
// smem float layout (offsets):
//   sL    0      (1024)   sU    1024   (1024)
//   sC2   2048   (2048)   sD12  4096   (1024)
//   sD21  5120   (1024)   sB2   6144   (2048)
//   sD22  8192   (1024)   sM    9216   (1024)
//   aug   10240  (2048)   sRinv 12288  (1024)
//   svr   13312  (5120)   mv    18432  (32)
// total 18464 floats = 73856 B
__global__ void ren_setup_a(const float* __restrict__ B2, const float* __restrict__ C2,
                            const float* __restrict__ D12, const float* __restrict__ L,
                            const float* __restrict__ U, const float* __restrict__ D21,
                            const float* __restrict__ gamma) {
    extern __shared__ float sf[];
    float* sL    = sf;
    float* sU    = sf + 1024;
    float* sC2   = sf + 2048;
    float* sD12  = sf + 4096;
    float* sD21  = sf + 5120;
    float* sB2   = sf + 6144;
    float* sD22  = sf + 8192;
    float* sM    = sf + 9216;
    float* aug   = sf + 10240;
    float* sRinv = sf + 12288;
    float* svr   = sf + 13312;
    float* mv    = sf + 18432;
    __shared__ int s_piv;
    __shared__ float s_ipv;
    const int tid = threadIdx.x, NT = blockDim.x;
    const float g = gamma[0];

    // stage inputs (coalesced gmem -> smem)
    for (int i = tid; i < 1024; i += NT) sL[i]   = L[i];
    for (int i = tid; i < 1024; i += NT) sU[i]   = U[i];
    for (int i = tid; i < 2048; i += NT) sC2[i]  = C2[i];
    for (int i = tid; i < 1024; i += NT) sD12[i] = D12[i];
    for (int i = tid; i < 1024; i += NT) sD21[i] = D21[i];
    for (int i = tid; i < 2048; i += NT) sB2[i]  = B2[i];
    __syncthreads();

    // D22 = (g+1) I + L^T L + (U - U^T)
    for (int idx = tid; idx < 1024; idx += NT) {
        int i = idx >> 5, j = idx & 31;
        float acc = (i == j) ? (g + 1.0f) : 0.0f;
        #pragma unroll 8
        for (int k = 0; k < 32; k++) acc += sL[k * 32 + i] * sL[k * 32 + j];
        acc += sU[i * 32 + j] - sU[j * 32 + i];
        sD22[idx] = acc;
        g_s.D22[idx] = acc;
    }
    __syncthreads();

    // Rcal augmented (32 x 64)
    for (int idx = tid; idx < 2048; idx += NT) {
        int i = idx >> 6, j = idx & 63;
        float v;
        if (j < 32) {
            float s = 0.0f;
            #pragma unroll 8
            for (int k = 0; k < 32; k++) s += sD22[k * 32 + i] * sD22[k * 32 + j];
            v = sD22[i * 32 + j] + sD22[j * 32 + i] - 1e-4f * s;
            if (i == j) v += -2.0f * g;
        } else v = ((j - 32) == i) ? 1.0f : 0.0f;
        aug[idx] = v;
    }
    __syncthreads();
    gj_invert_f32(aug, 32, mv, &s_piv, &s_ipv);
    for (int idx = tid; idx < 1024; idx += NT) {
        int i = idx >> 5, j = idx & 31;
        sRinv[idx] = aug[i * 64 + 32 + j];
    }
    // M = I - 1e-4 * D22^T
    for (int idx = tid; idx < 1024; idx += NT) {
        int i = idx >> 5, j = idx & 31;
        sM[idx] = ((i == j) ? 1.0f : 0.0f) - 1e-4f * sD22[j * 32 + i];
    }
    __syncthreads();

    // vec_r (160 x 32)
    for (int idx = tid; idx < 160 * 32; idx += NT) {
        int r = idx >> 5, c = idx & 31;
        float v;
        if (r < 64) {
            float s = 0.0f;
            #pragma unroll 8
            for (int k = 0; k < 32; k++) s += sM[c * 32 + k] * sC2[k * 64 + r];
            v = s;
        } else if (r < 96) {
            int rr = r - 64;
            float s = 0.0f;
            #pragma unroll 8
            for (int k = 0; k < 32; k++) s += sM[c * 32 + k] * sD21[k * 32 + rr];
            v = s - sD12[rr * 32 + c];
        } else v = sB2[(r - 96) * 32 + c];
        svr[idx] = v;
        g_s.vr[idx] = v;
    }
    __syncthreads();

    // T1 = vr @ Rinv (write straight to gmem; only setup_b reads it)
    for (int idx = tid; idx < 160 * 32; idx += NT) {
        int r = idx >> 5, c = idx & 31;
        float s = 0.0f;
        #pragma unroll 8
        for (int k = 0; k < 32; k++) s += svr[r * 32 + k] * sRinv[k * 32 + c];
        g_s.T1[idx] = s;
    }
}

// ---------------- Setup B (160 blocks) ----------------
__global__ void ren_setup_b(const float* __restrict__ X, const float* __restrict__ C2,
                            const float* __restrict__ D21) {
    __shared__ float Xa[160];
    __shared__ float T1a[32];
    __shared__ float vqa[32];
    const int a = blockIdx.x;
    const int tid = threadIdx.x;
    for (int k = tid; k < 160; k += blockDim.x) Xa[k] = X[k * 160 + a];
    if (tid < 32) {
        T1a[tid] = g_s.T1[a * 32 + tid];
        float vq = 0.0f;
        if (a < 64) vq = C2[tid * 64 + a];
        else if (a < 96) vq = D21[tid * 32 + (a - 64)];
        vqa[tid] = vq;
    }
    __syncthreads();
    for (int b = tid; b < 160; b += blockDim.x) {
        float gsum = 0.0f;
        for (int k = 0; k < 160; k++) gsum += Xa[k] * X[k * 160 + b];
        float pr = 0.0f;
        for (int c = 0; c < 32; c++) pr += T1a[c] * g_s.vr[b * 32 + c];
        float q = 0.0f;
        if (b < 96)
            for (int c = 0; c < 32; c++) {
                float vb = (b < 64) ? C2[c * 64 + b] : D21[c * 32 + (b - 64)];
                q += vqa[c] * vb;
            }
        float h = gsum + pr + 1e-4f * q;
        if (a == b) h += 1e-3f;
        g_s.H[a * 160 + b] = h;
    }
}

// ---------------- Setup CD (32 blocks x 512) ----------------
__global__ void ren_setup_cd(const float* __restrict__ Y, const float* __restrict__ B2,
                             const float* __restrict__ C2, const float* __restrict__ D12,
                             const float* __restrict__ D21) {
    extern __shared__ float sf[];
    float* aug = sf;                 // 64 x 128
    float* mv  = sf + 64 * 128;      // 64
    __shared__ int s_piv;
    __shared__ float s_ipv;
    __shared__ float CE[32 * 64];    // C2 @ Einv
    const int tid = threadIdx.x, NT = blockDim.x;

    for (int idx = tid; idx < 64 * 128; idx += NT) {
        int i = idx >> 7, j = idx & 127;
        float v;
        if (j < 64)
            v = 0.5f * (g_s.H[i * 160 + j] + g_s.H[(96 + i) * 160 + (96 + j)]
                        + Y[i * 64 + j] - Y[j * 64 + i]);
        else v = ((j - 64) == i) ? 1.0f : 0.0f;
        aug[idx] = v;
    }
    __syncthreads();
    gj_invert_f32(aug, 64, mv, &s_piv, &s_ipv);

#define EINV(r, c) (aug[(r) * 128 + 64 + (c)])
    // CE[i][n] = sum_m C2[i][m] * Einv[m][n]
    for (int idx = tid; idx < 32 * 64; idx += NT) {
        int i = idx >> 6, n = idx & 63;
        float s = 0.0f;
        for (int m = 0; m < 64; m++) s += C2[i * 64 + m] * EINV(m, n);
        CE[idx] = s;
    }
    __syncthreads();

    const int g = blockIdx.x * 512 + tid;   // 0..16383
    if (g < 8192) {
        // WX: float4[j*32+lane] = (rowA c0, rowA c1, rowB c0, rowB c1)
        int e = g;
        int comp = e & 3, r = e >> 2, j = r >> 5, lane = r & 31;
        int row = (comp < 2) ? lane : lane + 32;
        int c = comp & 1;
        float s = 0.0f;
        if (j < 16) {
            int col = 2 * j + c;
            for (int m = 0; m < 64; m++) s += EINV(row, m) * B2[m * 32 + col];
        } else if (j < 32) {
            int col = 2 * (j - 16) + c;
            for (int m = 0; m < 64; m++) s += EINV(row, m) * g_s.H[(96 + m) * 160 + 64 + col];
        } else {
            int col = 2 * (j - 32) + c;
            for (int m = 0; m < 64; m++) s += EINV(row, m) * g_s.H[(96 + m) * 160 + col];
        }
        g_params[OFF_WX + e] = s;
    } else if (g < 11264) {
        // WA: float2[j*32+i]; j<16 u (D12), else x (C1=-H21); * invLam[i]
        int e = g - 8192;
        int c = e & 1, r = e >> 1, j = r >> 5, i = r & 31;
        float invLam = 1.0f / (0.5f * g_s.H[(64 + i) * 160 + (64 + i)]);
        float v;
        if (j < 16) v = D12[i * 32 + 2 * j + c];
        else        v = -g_s.H[(64 + i) * 160 + 2 * (j - 16) + c];
        g_params[OFF_WA + e] = v * invLam;
    } else if (g < 15360) {
        // WYF: float2[j*32+i]; j<16 u: CE@B2 + D22; j<32 w: CE@H32 + D21;
        //                      j>=32 x: CE@H31
        int e = g - 11264;
        int c = e & 1, r = e >> 1, j = r >> 5, i = r & 31;
        int col;
        float val;
        if (j < 16)      { col = 2 * j + c;        val = g_s.D22[i * 32 + col]; }
        else if (j < 32) { col = 2 * (j - 16) + c; val = D21[i * 32 + col]; }
        else             { col = 2 * (j - 32) + c; val = 0.0f; }
        float acc = 0.0f;
        for (int n = 0; n < 64; n++) {
            float sv;
            if (j < 16)      sv = B2[n * 32 + col];
            else if (j < 32) sv = g_s.H[(96 + n) * 160 + 64 + col];
            else             sv = g_s.H[(96 + n) * 160 + col];
            acc += CE[i * 64 + n] * sv;
        }
        g_params[OFF_WY + e] = val + acc;
    } else {
        // DC: float[i*32+l] = (l>i) ? -H22[l][i]/Lam[l] : 0
        int e = g - 15360;
        int i = e >> 5, l = e & 31;
        float invLam = 1.0f / (0.5f * g_s.H[(64 + l) * 160 + (64 + l)]);
        g_params[OFF_DC + e] =
            (l > i) ? (-g_s.H[(64 + l) * 160 + (64 + i)] * invLam) : 0.0f;
    }
#undef EINV
}

// ---------------------------------------------------------------------------
// Main: R12/R13 ren_main VERBATIM (measured 955-981 us).
// ---------------------------------------------------------------------------
__global__ void __launch_bounds__(256, 1)
ren_main(const float* __restrict__ u_in, const float* __restrict__ x0,
         float* __restrict__ y_out) {
    extern __shared__ float sm[];
    {
        float4* dst = (float4*)sm;
        const float4* src = (const float4*)g_params;
        for (int i = threadIdx.x; i < 4096; i += blockDim.x) dst[i] = src[i];
    }
    const int warp = threadIdx.x >> 5;
    const int lane = threadIdx.x & 31;
    float* fS = sm + 16384 + warp * 384;
    const float4* SA = (const float4*)fS;
    __syncthreads();

    // register-cached weights
    u64t wa_r[48];
    #pragma unroll
    for (int j = 0; j < 48; j++)
        wa_r[j] = *(const u64t*)(sm + OFF_WA + (j * 32 + lane) * 2);
    float dc_r[32];
    #pragma unroll
    for (int i = 0; i < 32; i++)
        dc_r[i] = sm[OFF_DC + i * 32 + lane];

    const int e0 = (blockIdx.x * 8 + warp) * 2;
    const float* up0 = u_in + (size_t)(e0 + 0) * (T_STEPS * 32);
    const float* up1 = u_in + (size_t)(e0 + 1) * (T_STEPS * 32);
    float* yp0 = y_out + (size_t)(e0 + 0) * (T_STEPS * 32) + lane;
    float* yp1 = y_out + (size_t)(e0 + 1) * (T_STEPS * 32) + lane;

    // init x state (kp 64..95)
    {
        int ia = (64 + (lane >> 1)) * 4 + (lane & 1);
        int ib = (80 + (lane >> 1)) * 4 + (lane & 1);
        fS[ia]     = x0[(e0 + 0) * 64 + lane];
        fS[ia + 2] = x0[(e0 + 1) * 64 + lane];
        fS[ib]     = x0[(e0 + 0) * 64 + 32 + lane];
        fS[ib + 2] = x0[(e0 + 1) * 64 + 32 + lane];
    }
    float uc0 = up0[lane], uc1 = up1[lane];

    const int idxu = (32 + (lane >> 1)) * 4 + (lane & 1);
    const int idxw = (48 + (lane >> 1)) * 4 + (lane & 1);
    const int idxa = (64 + (lane >> 1)) * 4 + (lane & 1);
    const int idxb = (80 + (lane >> 1)) * 4 + (lane & 1);

#define LD2(p)  (*(const ulonglong2*)(p))
// a-phase state map: j<16 -> u at kp 32+j; j>=16 -> x at kp 48+j (=64..95)
#define MATA(kp, j) { \
    ulonglong2 s = LD2(SA + (kp)); \
    av0 = f2_fma(wa_r[j], s.x, av0); av1 = f2_fma(wa_r[j], s.y, av1); }
// combined x+y op: one state load feeds xn rowA, xn rowB, y row
#define MATXY(j) { \
    ulonglong2 wv = *(const ulonglong2*)(sm + OFF_WX + ((j) * 32 + lane) * 4); \
    u64t wy = *(const u64t*)(sm + OFF_WY + ((j) * 32 + lane) * 2); \
    ulonglong2 s  = LD2(SA + 32 + (j)); \
    xA0 = f2_fma(wv.x, s.x, xA0); xA1 = f2_fma(wv.x, s.y, xA1); \
    xB0 = f2_fma(wv.y, s.x, xB0); xB1 = f2_fma(wv.y, s.y, xB1); \
    yv0 = f2_fma(wy, s.x, yv0); yv1 = f2_fma(wy, s.y, yv1); }
#define CHAIN(i) { \
    float t0 = tanh_fast(a0), t1 = tanh_fast(a1); \
    t0 = __shfl_sync(0xffffffffu, t0, (i)); t1 = __shfl_sync(0xffffffffu, t1, (i)); \
    float d = dc_r[i]; \
    a0 = fmaf(d, t0, a0); a1 = fmaf(d, t1, a1); }

    for (int t = 0; t < T_STEPS; t++) {
        fS[idxu] = uc0; fS[idxu + 2] = uc1;
        int tn = (t < T_STEPS - 1) ? (t + 1) : t;
        float un0 = up0[tn * 32 + lane], un1 = up1[tn * 32 + lane];
        __syncwarp();

        // a-phase: j 0..15 u (kp 32..47), j 16..47 x (kp 64..95)
        u64t av0 = 0, av1 = 0;
        #pragma unroll
        for (int j = 0; j < 16; j++) MATA(32 + j, j);
        #pragma unroll
        for (int j = 16; j < 48; j++) MATA(48 + j, j);
        float a0 = f2_fold(av0), a1 = f2_fold(av1);

        // chain + interleaved w-independent MATXY ops
        u64t xA0 = 0, xA1 = 0, xB0 = 0, xB1 = 0;
        u64t yv0 = 0, yv1 = 0;
        #pragma unroll
        for (int i = 0; i < 16; i++) {
            CHAIN(i);
            { int m = 2 * i;     int op = (m < 16) ? m : m + 16; MATXY(op); }
            { int m = 2 * i + 1; int op = (m < 16) ? m : m + 16; MATXY(op); }
        }
        #pragma unroll
        for (int i = 16; i < 32; i++) { CHAIN(i); MATXY(i + 32); }

        // own w (a_lane final after iter=lane; later updates have zero coef)
        {
            float w0 = tanh_fast(a0), w1 = tanh_fast(a1);
            fS[idxw] = w0; fS[idxw + 2] = w1;
        }
        __syncwarp();

        // tail: w-part j16..31 (xn and y complete after this)
        #pragma unroll
        for (int j = 16; j < 32; j++) MATXY(j);
        fS[idxa] = f2_fold(xA0); fS[idxa + 2] = f2_fold(xA1);
        fS[idxb] = f2_fold(xB0); fS[idxb + 2] = f2_fold(xB1);
        yp0[t * 32] = f2_fold(yv0);
        yp1[t * 32] = f2_fold(yv1);

        uc0 = un0; uc1 = un1;
    }
}

// ---------------------------------------------------------------------------
extern "C" void kernel_launch(void* const* d_in, const int* in_sizes, int n_in,
                              void* d_out, int out_size) {
    const float* u_in  = (const float*)d_in[0];
    const float* x0    = (const float*)d_in[1];
    const float* X     = (const float*)d_in[2];
    const float* Y     = (const float*)d_in[3];
    const float* B2    = (const float*)d_in[4];
    const float* C2    = (const float*)d_in[5];
    const float* D12   = (const float*)d_in[6];
    const float* L     = (const float*)d_in[7];
    const float* U     = (const float*)d_in[8];
    const float* D21   = (const float*)d_in[9];
    const float* gamma = (const float*)d_in[10];
    float* y = (float*)d_out;

    const int setupa_smem = 18464 * 4 + 256;              // 74112 B (all-smem setup_a)
    const int setupcd_smem = 64 * 128 * 4 + 64 * 4 + 256; // 33280 B
    const int main_smem  = (16384 + 8 * 384) * 4;         // 77824 B

    cudaFuncSetAttribute(ren_setup_a,  cudaFuncAttributeMaxDynamicSharedMemorySize, setupa_smem);
    cudaFuncSetAttribute(ren_setup_cd, cudaFuncAttributeMaxDynamicSharedMemorySize, setupcd_smem);
    cudaFuncSetAttribute(ren_main,     cudaFuncAttributeMaxDynamicSharedMemorySize, main_smem);

    ren_setup_a<<<1, 256, setupa_smem>>>(B2, C2, D12, L, U, D21, gamma);
    ren_setup_b<<<160, 256>>>(X, C2, D21);
    ren_setup_cd<<<32, 512, setupcd_smem>>>(Y, B2, C2, D12, D21);
    ren_main<<<128, 256, main_smem>>>(u_in, x0, y);
}